// round 9
// baseline (speedup 1.0000x reference)
#include <cuda_runtime.h>
#include <cuda_bf16.h>
#include <math.h>

#define NB 8
#define NS 500
#define NU 128
#define NG 5
#define NC 100
#define NF 20
#define NH 5
#define GH 4
#define GD 32

typedef unsigned long long ull;

// ---------------- packed f32x2 helpers (sm_100+) ----------------
__device__ __forceinline__ ull pk2(float a, float b) {
    ull r; asm("mov.b64 %0,{%1,%2};" : "=l"(r) : "f"(a), "f"(b)); return r;
}
__device__ __forceinline__ void up2(float& a, float& b, ull p) {
    asm("mov.b64 {%0,%1},%2;" : "=f"(a), "=f"(b) : "l"(p));
}
__device__ __forceinline__ ull fma2(ull a, ull b, ull c) {
    ull d; asm("fma.rn.f32x2 %0,%1,%2,%3;" : "=l"(d) : "l"(a), "l"(b), "l"(c)); return d;
}
__device__ __forceinline__ ull mul2(ull a, ull b) {
    ull d; asm("mul.rn.f32x2 %0,%1,%2;" : "=l"(d) : "l"(a), "l"(b)); return d;
}
__device__ __forceinline__ ull add2(ull a, ull b) {
    ull d; asm("add.rn.f32x2 %0,%1,%2;" : "=l"(d) : "l"(a), "l"(b)); return d;
}
__device__ __forceinline__ float ex2f_(float x) {
    float y; asm("ex2.approx.ftz.f32 %0,%1;" : "=f"(y) : "f"(x)); return y;
}
__device__ __forceinline__ float rcpf_(float x) {
    float y; asm("rcp.approx.ftz.f32 %0,%1;" : "=f"(y) : "f"(x)); return y;
}

// ---------------- cp.async helpers ----------------
__device__ __forceinline__ unsigned s2u(const void* p) {
    return (unsigned)__cvta_generic_to_shared(p);
}
__device__ __forceinline__ void cpa16(unsigned dst, const void* src) {
    asm volatile("cp.async.cg.shared.global [%0], [%1], 16;\n" :: "r"(dst), "l"(src));
}
__device__ __forceinline__ void cpa_commit() { asm volatile("cp.async.commit_group;\n" ::); }
template <int N>
__device__ __forceinline__ void cpa_wait() { asm volatile("cp.async.wait_group %0;\n" :: "n"(N)); }

#define LOG2E 1.4426950408889634f

// scratch (device globals)
__device__ float g_scr[NB * NC * NU];         // [B,C,U]
__device__ float gq_scr[NB * GH * NC * GD];
__device__ float gk_scr[NB * GH * NC * GD];
__device__ float gv_scr[NB * GH * NC * GD];

// ---------------------------------------------------------------------------
// Kernel 1 (fused chunk MHA + output proj): block = (b,c), 160 threads.
// Warp w = head w: 32 lanes x 4 u each. Heads' outputs -> SMEM, then the
// epilogue (threads 0-127) does out-proj + leaky + mean + pos -> g.
// exp: uu==0 via FMA-pipe poly, uu 1-3 via MUFU ex2 (pipe balance p=1).
// ---------------------------------------------------------------------------
__global__ __launch_bounds__(160, 3) void k1_fused(
    const float* __restrict__ x,
    const float* __restrict__ wq, const float* __restrict__ bq,
    const float* __restrict__ wk, const float* __restrict__ bk,
    const float* __restrict__ wv, const float* __restrict__ bv,
    const float* __restrict__ wo, const float* __restrict__ bo,
    const float* __restrict__ pos, float* __restrict__ out)
{
    const int bc = blockIdx.x;
    const int b = bc / NC;
    const int c = bc - b * NC;
    const int t = threadIdx.x;
    const int w = t >> 5;      // head
    const int lane = t & 31;

    __shared__ __align__(16) ull wqp[NH][NF], wkp[NH][NF], wvp[NH][NF];
    __shared__ float bqs[NH][2], bks[NH][2], bvs[NH][2];
    __shared__ __align__(16) float xs[NG][NU];
    __shared__ __align__(16) float ks0[NH][NU], ks1[NH][NU];
    __shared__ __align__(16) float vs0[NH][NU], vs1[NH][NU];
    __shared__ __align__(16) float os[10][NU];
    __shared__ __align__(16) float wo_s[200];
    __shared__ __align__(16) float bo_s[20];

    // cooperative loads
    for (int i = t; i < 100; i += 160) {
        const int hh = i / 20, f = i - hh * 20;
        const int base = c * 200 + f * 10 + 2 * hh;
        wqp[hh][f] = *(const ull*)(wq + base);
        wkp[hh][f] = *(const ull*)(wk + base);
        wvp[hh][f] = *(const ull*)(wv + base);
    }
    if (t < 10) {
        bqs[t >> 1][t & 1] = bq[c * 10 + t];
        bks[t >> 1][t & 1] = bk[c * 10 + t];
        bvs[t >> 1][t & 1] = bv[c * 10 + t];
    }
    for (int i = t; i < 200; i += 160) wo_s[i] = wo[c * 200 + i];
    if (t < 20) bo_s[t] = bo[c * 20 + t];
    {
        const float* xp = x + ((size_t)b * NS + (size_t)c * NG) * NU;
        for (int i = t; i < NG * NU; i += 160) xs[i / NU][i % NU] = xp[i];
    }
    __syncthreads();

    const int PI[10] = {0, 0, 0, 0, 1, 1, 1, 2, 2, 3};
    const int PJ[10] = {1, 2, 3, 4, 2, 3, 4, 3, 4, 4};

    // ---- per-warp head projections (4 u per lane) ----
    float q0a[4], q1a[4];
#pragma unroll
    for (int uu = 0; uu < 4; uu++) {
        const int u = lane + uu * 32;
        float xv[NG];
#pragma unroll
        for (int k = 0; k < NG; k++) xv[k] = xs[k][u];
        ull aq = pk2(bqs[w][0], bqs[w][1]);
        ull ak = pk2(bks[w][0], bks[w][1]);
        ull av = pk2(bvs[w][0], bvs[w][1]);
#pragma unroll
        for (int m = 0; m < 10; m++) {
            const ull h0 = pk2(xv[PI[m]], xv[PI[m]]);
            const ull h1 = pk2(xv[PJ[m]], xv[PJ[m]]);
            aq = fma2(h0, wqp[w][2 * m], aq);
            ak = fma2(h0, wkp[w][2 * m], ak);
            av = fma2(h0, wvp[w][2 * m], av);
            aq = fma2(h1, wqp[w][2 * m + 1], aq);
            ak = fma2(h1, wkp[w][2 * m + 1], ak);
            av = fma2(h1, wvp[w][2 * m + 1], av);
        }
        // uu 0: natural-e poly; uu 1-3: ex2 with log2e folded
        const float QS = (uu < 1) ? 0.7071067811865476f
                                  : 0.7071067811865476f * LOG2E;
        float lo, hi;
        up2(lo, hi, aq); q0a[uu] = lo * QS; q1a[uu] = hi * QS;
        up2(lo, hi, ak); ks0[w][u] = lo; ks1[w][u] = hi;
        up2(lo, hi, av); vs0[w][u] = lo; vs1[w][u] = hi;
    }
    __syncwarp();   // each warp only reads its own head's K/V

    // ---- attention mainloop ----
    const ulonglong2* __restrict__ k0p = (const ulonglong2*)&ks0[w][0];
    const ulonglong2* __restrict__ k1p = (const ulonglong2*)&ks1[w][0];
    const ulonglong2* __restrict__ v0p = (const ulonglong2*)&vs0[w][0];
    const ulonglong2* __restrict__ v1p = (const ulonglong2*)&vs1[w][0];

    const ull Z = pk2(0.f, 0.f);
    const ull C0 = pk2(1.f, 1.f);
    const ull C2 = pk2(0.5f, 0.5f);
    const ull C3 = pk2(1.f / 6.f, 1.f / 6.f);
    const ull C4 = pk2(1.f / 24.f, 1.f / 24.f);

    ull q0p[4], q1p[4];
#pragma unroll
    for (int uu = 0; uu < 4; uu++) {
        q0p[uu] = pk2(q0a[uu], q0a[uu]);
        q1p[uu] = pk2(q1a[uu], q1a[uu]);
    }
    ull L[4], O00[4], O01[4], O10[4], O11[4];
#pragma unroll
    for (int uu = 0; uu < 4; uu++) {
        L[uu] = O00[uu] = O01[uu] = O10[uu] = O11[uu] = Z;
    }

#pragma unroll 2
    for (int i = 0; i < 32; i++) {
        const ulonglong2 K0 = k0p[i], K1 = k1p[i];
        const ulonglong2 V0 = v0p[i], V1 = v1p[i];
#pragma unroll
        for (int uu = 0; uu < 4; uu++) {
            ull s0 = fma2(q0p[uu], K0.x, mul2(q1p[uu], K1.x));
            ull s1 = fma2(q0p[uu], K0.y, mul2(q1p[uu], K1.y));
            ull e0, e1;
            if (uu < 1) {
                ull p0 = fma2(s0, C4, C3);
                ull p1 = fma2(s1, C4, C3);
                p0 = fma2(s0, p0, C2);
                p1 = fma2(s1, p1, C2);
                p0 = fma2(s0, p0, C0);
                p1 = fma2(s1, p1, C0);
                e0 = fma2(s0, p0, C0);
                e1 = fma2(s1, p1, C0);
            } else {
                float a0, a1, a2, a3;
                up2(a0, a1, s0); up2(a2, a3, s1);
                e0 = pk2(ex2f_(a0), ex2f_(a1));
                e1 = pk2(ex2f_(a2), ex2f_(a3));
            }
            L[uu] = add2(L[uu], add2(e0, e1));
            O00[uu] = fma2(e0, V0.x, O00[uu]);
            O01[uu] = fma2(e1, V0.y, O01[uu]);
            O10[uu] = fma2(e0, V1.x, O10[uu]);
            O11[uu] = fma2(e1, V1.y, O11[uu]);
        }
    }

#pragma unroll
    for (int uu = 0; uu < 4; uu++) {
        const int u = lane + uu * 32;
        float x0, x1, x2, x3;
        up2(x0, x1, L[uu]);
        const float inv = rcpf_(x0 + x1);
        up2(x0, x1, O00[uu]); up2(x2, x3, O01[uu]);
        os[2 * w][u] = ((x0 + x1) + (x2 + x3)) * inv;
        up2(x0, x1, O10[uu]); up2(x2, x3, O11[uu]);
        os[2 * w + 1][u] = ((x0 + x1) + (x2 + x3)) * inv;
    }
    __syncthreads();

    // ---- epilogue: out-proj + leaky + mean + pos (threads 0-127) ----
    if (t < NU) {
        float ov[10];
#pragma unroll
        for (int j = 0; j < 10; j++) ov[j] = os[j][t];
        float xv[NG];
#pragma unroll
        for (int k = 0; k < NG; k++) xv[k] = xs[k][t];

        ull am[10];
#pragma unroll
        for (int p = 0; p < 10; p++) am[p] = pk2(bo_s[2 * p], bo_s[2 * p + 1]);
#pragma unroll
        for (int j = 0; j < 10; j++) {
            const ull op = pk2(ov[j], ov[j]);
#pragma unroll
            for (int p = 0; p < 10; p++)
                am[p] = fma2(op, *(const ull*)&wo_s[j * 20 + 2 * p], am[p]);
        }
        float acc = 0.f;
#pragma unroll
        for (int p = 0; p < 10; p++) {
            float m0, m1;
            up2(m0, m1, am[p]);
            float a0 = xv[PI[p]] + m0;
            float a1 = xv[PJ[p]] + m1;
            acc += (a0 > 0.f) ? a0 : 0.3f * a0;
            acc += (a1 > 0.f) ? a1 : 0.3f * a1;
        }
        const float gval = acc * (1.0f / 20.0f) + pos[c * NU + t];
        g_scr[bc * NU + t] = gval;
        out[bc * NU + t] = gval;   // seed residual; k3 atomically adds g_attn
    }
}

// ---------------------------------------------------------------------------
// Kernel 2: graph q/k/v projections. grid = 8*20 (5 c per block), 128 thr.
// ---------------------------------------------------------------------------
#define K2_CHUNK 8
#define K2_NCH (NU / K2_CHUNK)

__global__ __launch_bounds__(128) void k2_graph_proj(
    const float* __restrict__ gwq, const float* __restrict__ gbq,
    const float* __restrict__ gwk, const float* __restrict__ gbk,
    const float* __restrict__ gwv, const float* __restrict__ gbv)
{
    const int bid = blockIdx.x;
    const int b = bid / 20;
    const int c0 = (bid - b * 20) * 5;
    const int t = threadIdx.x;

    __shared__ __align__(16) float bwq[2][K2_CHUNK][128];
    __shared__ __align__(16) float bwk[2][K2_CHUNK][128];
    __shared__ __align__(16) float bwv[2][K2_CHUNK][128];
    __shared__ __align__(16) ull gtp[128][2];
    __shared__ __align__(16) float gsc[128];

    auto fill = [&](int ch) {
        const int pb = ch & 1;
        const float4* sq = (const float4*)(gwq + ch * K2_CHUNK * 128);
        const float4* sk = (const float4*)(gwk + ch * K2_CHUNK * 128);
        const float4* sv = (const float4*)(gwv + ch * K2_CHUNK * 128);
        unsigned dq = s2u(&bwq[pb][0][0]);
        unsigned dk = s2u(&bwk[pb][0][0]);
        unsigned dv = s2u(&bwv[pb][0][0]);
        cpa16(dq + t * 16, sq + t);
        cpa16(dq + (t + 128) * 16, sq + t + 128);
        cpa16(dk + t * 16, sk + t);
        cpa16(dk + (t + 128) * 16, sk + t + 128);
        cpa16(dv + t * 16, sv + t);
        cpa16(dv + (t + 128) * 16, sv + t + 128);
    };
    fill(0);
    cpa_commit();
    fill(1);
    cpa_commit();

    {
        float tmp[5];
#pragma unroll
        for (int cc = 0; cc < 5; cc++)
            tmp[cc] = g_scr[(b * NC + c0 + cc) * NU + t];
        gtp[t][0] = pk2(tmp[0], tmp[1]);
        gtp[t][1] = pk2(tmp[2], tmp[3]);
        gsc[t] = tmp[4];
    }

    ull aq[2], ak[2], av[2];
    float aqs, aks, avs;
    {
        const float bqv = gbq[t], bkv = gbk[t], bvv = gbv[t];
        aq[0] = aq[1] = pk2(bqv, bqv);
        ak[0] = ak[1] = pk2(bkv, bkv);
        av[0] = av[1] = pk2(bvv, bvv);
        aqs = bqv; aks = bkv; avs = bvv;
    }

    for (int ch = 0; ch < K2_NCH; ch++) {
        // final chunk: drain fully (its own group is the only one pending)
        if (ch + 1 < K2_NCH) { cpa_wait<1>(); } else { cpa_wait<0>(); }
        __syncthreads();
        const int pb = ch & 1;
#pragma unroll
        for (int uu = 0; uu < K2_CHUNK; uu++) {
            const int u = ch * K2_CHUNK + uu;
            const float wqv = bwq[pb][uu][t];
            const float wkv = bwk[pb][uu][t];
            const float wvv = bwv[pb][uu][t];
            const ull wq2 = pk2(wqv, wqv);
            const ull wk2 = pk2(wkv, wkv);
            const ull wv2 = pk2(wvv, wvv);
            const float gg = gsc[u];
#pragma unroll
            for (int p = 0; p < 2; p++) {
                const ull gp = gtp[u][p];
                aq[p] = fma2(wq2, gp, aq[p]);
                ak[p] = fma2(wk2, gp, ak[p]);
                av[p] = fma2(wv2, gp, av[p]);
            }
            aqs = fmaf(wqv, gg, aqs);
            aks = fmaf(wkv, gg, aks);
            avs = fmaf(wvv, gg, avs);
        }
        __syncthreads();
        if (ch + 2 < K2_NCH) {
            fill(ch + 2);
            cpa_commit();
        }
    }

    const float QS = 0.17677669529663687f * LOG2E;
    const int h = t >> 5, d = t & 31;
    const int rowbase = (b * GH + h) * NC;
#pragma unroll
    for (int p = 0; p < 2; p++) {
        float lo, hi;
        up2(lo, hi, aq[p]);
        gq_scr[(rowbase + c0 + 2 * p) * GD + d] = lo * QS;
        gq_scr[(rowbase + c0 + 2 * p + 1) * GD + d] = hi * QS;
        up2(lo, hi, ak[p]);
        gk_scr[(rowbase + c0 + 2 * p) * GD + d] = lo;
        gk_scr[(rowbase + c0 + 2 * p + 1) * GD + d] = hi;
        up2(lo, hi, av[p]);
        gv_scr[(rowbase + c0 + 2 * p) * GD + d] = lo;
        gv_scr[(rowbase + c0 + 2 * p + 1) * GD + d] = hi;
    }
    gq_scr[(rowbase + c0 + 4) * GD + d] = aqs * QS;
    gk_scr[(rowbase + c0 + 4) * GD + d] = aks;
    gv_scr[(rowbase + c0 + 4) * GD + d] = avs;
}

// ---------------------------------------------------------------------------
// Kernel 3 (graph attn + out-proj): block = ((b*GH+h)*20 + qt5), 160 thr.
// ---------------------------------------------------------------------------
#define QT 5

__global__ __launch_bounds__(160) void k3_graph_attn_out(
    const float* __restrict__ gwo, const float* __restrict__ gbo,
    float* __restrict__ out)
{
    const int bid = blockIdx.x;
    const int bh = bid / 20;
    const int qt = (bid - bh * 20) * QT;
    const int b = bh >> 2;
    const int h = bh & 3;
    const int t = threadIdx.x;

    __shared__ float qs[QT * GD];
    __shared__ float gkt[GD * 101];      // padded rows (101) -> conflict-free
    __shared__ float gv_s[NC * GD];
    __shared__ float sc[QT * NC];
    __shared__ float o_s[QT][GD];
    __shared__ float linv[QT];

    float wcol[GD];
    if (t < 128) {
#pragma unroll
        for (int d = 0; d < GD; d++)
            wcol[d] = gwo[(h * GD + d) * NU + t];
    }

    const float* __restrict__ gq_g = gq_scr + (bh * NC + qt) * GD;
    const float* __restrict__ gk_g = gk_scr + bh * NC * GD;
    const float* __restrict__ gv_g = gv_scr + bh * NC * GD;

    for (int i = t; i < QT * GD; i += 160) qs[i] = gq_g[i];
    for (int i = t; i < NC * GD; i += 160) {
        gv_s[i] = gv_g[i];
        const int cq = i >> 5, d = i & 31;
        gkt[d * 101 + cq] = gk_g[i];
    }
    __syncthreads();

    // e = exp2(q.k)
    for (int i = t; i < QT * NC; i += 160) {
        const int q = i / NC, k = i - q * NC;
        float s = 0.f;
#pragma unroll
        for (int d = 0; d < GD; d++)
            s = fmaf(qs[q * GD + d], gkt[d * 101 + k], s);
        sc[i] = ex2f_(s);
    }
    __syncthreads();

    // row sums: warp w = row w
    {
        const int q = t >> 5, l = t & 31;
        float s = sc[q * NC + l] + sc[q * NC + l + 32] + sc[q * NC + l + 64];
        if (l < 4) s += sc[q * NC + l + 96];
        s += __shfl_xor_sync(0xffffffffu, s, 16);
        s += __shfl_xor_sync(0xffffffffu, s, 8);
        s += __shfl_xor_sync(0xffffffffu, s, 4);
        s += __shfl_xor_sync(0xffffffffu, s, 2);
        s += __shfl_xor_sync(0xffffffffu, s, 1);
        if (l == 0) linv[q] = rcpf_(s);
    }
    __syncthreads();

    // o[q,d]: one output per thread (warp = q, lane = d)
    {
        const int q = t >> 5, d = t & 31;
        float acc = 0.f;
#pragma unroll 4
        for (int k = 0; k < NC; k++)
            acc = fmaf(sc[q * NC + k], gv_s[k * GD + d], acc);
        o_s[q][d] = acc * linv[q];
    }
    __syncthreads();

    // out[b, qt+q, t] += sum_d o[q,d] * wcol[d]  (+gbo once, via h==0)
    if (t < 128) {
        const float bias = (h == 0) ? gbo[t] : 0.f;
#pragma unroll
        for (int q = 0; q < QT; q++) {
            float acc = bias;
#pragma unroll
            for (int d = 0; d < GD; d++)
                acc = fmaf(o_s[q][d], wcol[d], acc);
            atomicAdd(&out[(b * NC + qt + q) * NU + t], acc);
        }
    }
}

// ---------------------------------------------------------------------------
extern "C" void kernel_launch(void* const* d_in, const int* in_sizes, int n_in,
                              void* d_out, int out_size)
{
    const float* x   = (const float*)d_in[0];
    const float* wq  = (const float*)d_in[1];
    const float* bq  = (const float*)d_in[2];
    const float* wk  = (const float*)d_in[3];
    const float* bk  = (const float*)d_in[4];
    const float* wv  = (const float*)d_in[5];
    const float* bv  = (const float*)d_in[6];
    const float* wo  = (const float*)d_in[7];
    const float* bo  = (const float*)d_in[8];
    const float* pos = (const float*)d_in[9];
    const float* gwq = (const float*)d_in[10];
    const float* gbq = (const float*)d_in[11];
    const float* gwk = (const float*)d_in[12];
    const float* gbk = (const float*)d_in[13];
    const float* gwv = (const float*)d_in[14];
    const float* gbv = (const float*)d_in[15];
    const float* gwo = (const float*)d_in[16];
    const float* gbo = (const float*)d_in[17];
    float* out = (float*)d_out;

    k1_fused<<<NB * NC, 160>>>(x, wq, bq, wk, bk, wv, bv, wo, bo, pos, out);
    k2_graph_proj<<<NB * 20, 128>>>(gwq, gbq, gwk, gbk, gwv, gbv);
    k3_graph_attn_out<<<NB * GH * 20, 160>>>(gwo, gbo, out);
}